// round 2
// baseline (speedup 1.0000x reference)
#include <cuda_runtime.h>
#include <cstdint>

// Problem constants (fixed by the dataset)
#define NN   100000      // nodes
#define EE   100000      // hyperedges
#define NNZV 800000      // nonzeros
#define RRK  4           // ranks
#define FFT  64          // features
#define F4   (FFT/4)     // 16 float4 per feature row

// Scratch: he_feat[E][F]  (25.6 MB) — device global, no allocation allowed.
__device__ __align__(16) float g_he_feat[(size_t)EE * FFT];

__device__ __forceinline__ void red_add_v4(float* addr, float a, float b, float c, float d) {
    asm volatile("red.global.add.v4.f32 [%0], {%1,%2,%3,%4};"
                 :: "l"(addr), "f"(a), "f"(b), "f"(c), "f"(d) : "memory");
}

// ---------------------------------------------------------------------------
// Kernel 0: init. Zero g_he_feat; zero out ranks 0..R-2; out rank R-1 = x.
// ---------------------------------------------------------------------------
__global__ void k_init(float4* __restrict__ out4, const float4* __restrict__ x4) {
    unsigned i = blockIdx.x * blockDim.x + threadIdx.x;
    const unsigned OUT4 = (unsigned)NN * RRK * F4;   // 6,400,000
    const unsigned HE4  = (unsigned)EE * F4;         // 1,600,000
    if (i < HE4) {
        reinterpret_cast<float4*>(g_he_feat)[i] = make_float4(0.f, 0.f, 0.f, 0.f);
    }
    if (i < OUT4) {
        unsigned row = i / (RRK * F4);
        unsigned j   = i - row * (RRK * F4);   // 0..63
        unsigned rank = j >> 4;                // j / 16
        if (rank == RRK - 1) {
            out4[i] = x4[row * F4 + (j & 15)];
        } else {
            out4[i] = make_float4(0.f, 0.f, 0.f, 0.f);
        }
    }
}

// ---------------------------------------------------------------------------
// Kernel 1: he_feat[cols[k]] += vals[k] * x[rows[k]]
// 16 threads per nnz; each handles one float4 of the 64-feature row.
// ---------------------------------------------------------------------------
__global__ void k_scatter_fwd(const float4* __restrict__ x4,
                              const float* __restrict__ vals,
                              const int* __restrict__ rows,
                              const int* __restrict__ cols) {
    unsigned t = blockIdx.x * blockDim.x + threadIdx.x;
    unsigned k = t >> 4;
    unsigned lane = t & 15;
    if (k >= NNZV) return;
    int row = __ldg(&rows[k]);
    int col = __ldg(&cols[k]);
    float v = __ldg(&vals[k]);
    float4 xv = x4[(unsigned)row * F4 + lane];
    red_add_v4(&g_he_feat[(unsigned)col * FFT + lane * 4],
               xv.x * v, xv.y * v, xv.z * v, xv.w * v);
}

// ---------------------------------------------------------------------------
// Kernel 2: for r in 0..R-2:
//   out[rows[k], r] += vals[k] * rank_masks[r, he_idxs[cols[k]]] * he_feat[cols[k]]
// (rank R-1 is overwritten by x in the reference, so we skip it entirely)
// ---------------------------------------------------------------------------
__global__ void k_scatter_bwd(float* __restrict__ out,
                              const float* __restrict__ rank_masks,
                              const float* __restrict__ vals,
                              const int* __restrict__ he_idxs,
                              const int* __restrict__ rows,
                              const int* __restrict__ cols) {
    unsigned t = blockIdx.x * blockDim.x + threadIdx.x;
    unsigned k = t >> 4;
    unsigned lane = t & 15;
    if (k >= NNZV) return;
    int row = __ldg(&rows[k]);
    int col = __ldg(&cols[k]);
    float v = __ldg(&vals[k]);
    int he = __ldg(&he_idxs[col]);

    float r0 = __ldg(&rank_masks[(unsigned)he]) * v;
    float r1 = __ldg(&rank_masks[(unsigned)EE + he]) * v;
    float r2 = __ldg(&rank_masks[2u * EE + he]) * v;

    float4 hf = reinterpret_cast<const float4*>(g_he_feat)[(unsigned)col * F4 + lane];

    float* base = out + (size_t)row * (RRK * FFT) + lane * 4;
    red_add_v4(base + 0 * FFT, hf.x * r0, hf.y * r0, hf.z * r0, hf.w * r0);
    red_add_v4(base + 1 * FFT, hf.x * r1, hf.y * r1, hf.z * r1, hf.w * r1);
    red_add_v4(base + 2 * FFT, hf.x * r2, hf.y * r2, hf.z * r2, hf.w * r2);
}

// ---------------------------------------------------------------------------
// Launch. Input order (metadata): x, rank_masks, vals, he_idxs, rows, cols.
// NOTE: JAX without x64 downcasts the "int64" index arrays to int32.
// ---------------------------------------------------------------------------
extern "C" void kernel_launch(void* const* d_in, const int* in_sizes, int n_in,
                              void* d_out, int out_size) {
    const float* x   = (const float*)d_in[0];
    const float* rm  = (const float*)d_in[1];
    const float* val = (const float*)d_in[2];
    const int*   he  = (const int*)d_in[3];
    const int*   rw  = (const int*)d_in[4];
    const int*   cl  = (const int*)d_in[5];
    float* out = (float*)d_out;

    const unsigned OUT4 = (unsigned)NN * RRK * F4;       // 6.4M float4
    const int TPB = 256;

    k_init<<<(OUT4 + TPB - 1) / TPB, TPB>>>((float4*)out, (const float4*)x);

    const unsigned WORK = (unsigned)NNZV * 16;           // 12.8M threads
    k_scatter_fwd<<<(WORK + TPB - 1) / TPB, TPB>>>((const float4*)x, val, rw, cl);

    k_scatter_bwd<<<(WORK + TPB - 1) / TPB, TPB>>>(out, rm, val, he, rw, cl);
}

// round 3
// speedup vs baseline: 1.4967x; 1.4967x over previous
#include <cuda_runtime.h>

// Problem constants (fixed by the dataset)
#define NN   100000      // nodes
#define EE   100000      // hyperedges
#define NNZV 800000      // nonzeros
#define FFT  64          // features
#define F4   16          // float4 per feature row

#define MBK   (NN + EE)                      // 200000 buckets: [0,NN)=rows, [NN,MBK)=cols
#define CHUNK 1024
#define NBLK  ((MBK + CHUNK - 1) / CHUNK)    // 196

// ---- device scratch (no allocation allowed) ----
__device__ __align__(16) float g_he_feat[(size_t)EE * FFT];   // 25.6 MB
__device__ int   g_cnt[MBK];
__device__ int   g_cur[MBK];
__device__ int   g_off[MBK];
__device__ int   g_bsum[NBLK];
__device__ int   g_bpre[256];
__device__ int   g_adj_idx[2 * NNZV];        // row-CSR: col per slot; col-CSR: row per slot
__device__ float g_adj_val[2 * NNZV];

// ---------------------------------------------------------------------------
// CSR build
// ---------------------------------------------------------------------------
__global__ void k_zero() {
    unsigned i = blockIdx.x * blockDim.x + threadIdx.x;
    if (i < MBK) { g_cnt[i] = 0; g_cur[i] = 0; }
}

__global__ void k_count(const int* __restrict__ rows, const int* __restrict__ cols) {
    unsigned k = blockIdx.x * blockDim.x + threadIdx.x;
    if (k >= NNZV) return;
    atomicAdd(&g_cnt[rows[k]], 1);
    atomicAdd(&g_cnt[NN + cols[k]], 1);
}

// block-local exclusive scan of g_cnt chunks; block totals to g_bsum
__global__ void k_scan1() {
    __shared__ int tsum[256];
    int b = blockIdx.x, t = threadIdx.x;
    int base = b * CHUNK + t * 4;
    int v0 = (base + 0 < MBK) ? g_cnt[base + 0] : 0;
    int v1 = (base + 1 < MBK) ? g_cnt[base + 1] : 0;
    int v2 = (base + 2 < MBK) ? g_cnt[base + 2] : 0;
    int v3 = (base + 3 < MBK) ? g_cnt[base + 3] : 0;
    tsum[t] = v0 + v1 + v2 + v3;
    __syncthreads();
    for (int d = 1; d < 256; d <<= 1) {
        int add = (t >= d) ? tsum[t - d] : 0;
        __syncthreads();
        tsum[t] += add;
        __syncthreads();
    }
    int run = (t == 0) ? 0 : tsum[t - 1];
    if (base + 0 < MBK) g_off[base + 0] = run;  run += v0;
    if (base + 1 < MBK) g_off[base + 1] = run;  run += v1;
    if (base + 2 < MBK) g_off[base + 2] = run;  run += v2;
    if (base + 3 < MBK) g_off[base + 3] = run;  run += v3;
    if (t == 255) g_bsum[b] = tsum[255];
}

// single-block exclusive scan of block totals
__global__ void k_scan2() {
    __shared__ int sh[256];
    int t = threadIdx.x;
    sh[t] = (t < NBLK) ? g_bsum[t] : 0;
    __syncthreads();
    for (int d = 1; d < 256; d <<= 1) {
        int add = (t >= d) ? sh[t - d] : 0;
        __syncthreads();
        sh[t] += add;
        __syncthreads();
    }
    g_bpre[t] = (t == 0) ? 0 : sh[t - 1];
}

__global__ void k_scan3() {
    unsigned i = blockIdx.x * blockDim.x + threadIdx.x;
    if (i < MBK) g_off[i] += g_bpre[i / CHUNK];
}

__global__ void k_fill(const int* __restrict__ rows, const int* __restrict__ cols,
                       const float* __restrict__ vals) {
    unsigned k = blockIdx.x * blockDim.x + threadIdx.x;
    if (k >= NNZV) return;
    int r = rows[k], c = cols[k];
    float v = vals[k];
    int s1 = g_off[r] + atomicAdd(&g_cur[r], 1);
    g_adj_idx[s1] = c; g_adj_val[s1] = v;
    int s2 = g_off[NN + c] + atomicAdd(&g_cur[NN + c], 1);
    g_adj_idx[s2] = r; g_adj_val[s2] = v;
}

// ---------------------------------------------------------------------------
// Pass 1 (gather): he_feat[e] = sum over incident nnz of v * x[row]
// 16 threads per hyperedge, one float4 lane each.
// ---------------------------------------------------------------------------
__global__ void k_fwd(const float4* __restrict__ x4) {
    unsigned t = blockIdx.x * blockDim.x + threadIdx.x;
    unsigned e = t >> 4, lane = t & 15;
    if (e >= EE) return;
    int beg = g_off[NN + e];
    int num = g_cnt[NN + e];
    float4 acc = make_float4(0.f, 0.f, 0.f, 0.f);
    #pragma unroll 2
    for (int s = beg; s < beg + num; s++) {
        int r   = g_adj_idx[s];
        float v = g_adj_val[s];
        float4 xv = x4[(unsigned)r * F4 + lane];
        acc.x += v * xv.x; acc.y += v * xv.y;
        acc.z += v * xv.z; acc.w += v * xv.w;
    }
    reinterpret_cast<float4*>(g_he_feat)[e * F4 + lane] = acc;
}

// ---------------------------------------------------------------------------
// Pass 2 (gather): out[n,r] = sum v * rm[r,he_idxs[col]] * he_feat[col], r<3
//                  out[n,3] = x[n]
// 16 threads per node, one float4 lane each.
// ---------------------------------------------------------------------------
__global__ void k_bwd(float4* __restrict__ out4,
                      const float4* __restrict__ x4,
                      const float* __restrict__ rank_masks,
                      const int* __restrict__ he_idxs) {
    unsigned t = blockIdx.x * blockDim.x + threadIdx.x;
    unsigned n = t >> 4, lane = t & 15;
    if (n >= NN) return;
    int beg = g_off[n];
    int num = g_cnt[n];
    float4 a0 = make_float4(0.f, 0.f, 0.f, 0.f);
    float4 a1 = a0, a2 = a0;
    #pragma unroll 2
    for (int s = beg; s < beg + num; s++) {
        int c   = g_adj_idx[s];
        float v = g_adj_val[s];
        int he  = __ldg(&he_idxs[c]);
        float r0 = __ldg(&rank_masks[(unsigned)he]) * v;
        float r1 = __ldg(&rank_masks[(unsigned)EE + he]) * v;
        float r2 = __ldg(&rank_masks[2u * EE + he]) * v;
        float4 hf = reinterpret_cast<const float4*>(g_he_feat)[(unsigned)c * F4 + lane];
        a0.x += r0 * hf.x; a0.y += r0 * hf.y; a0.z += r0 * hf.z; a0.w += r0 * hf.w;
        a1.x += r1 * hf.x; a1.y += r1 * hf.y; a1.z += r1 * hf.z; a1.w += r1 * hf.w;
        a2.x += r2 * hf.x; a2.y += r2 * hf.y; a2.z += r2 * hf.z; a2.w += r2 * hf.w;
    }
    float4* base = out4 + (size_t)n * 4 * F4 + lane;
    base[0 * F4] = a0;
    base[1 * F4] = a1;
    base[2 * F4] = a2;
    base[3 * F4] = x4[n * F4 + lane];
}

// ---------------------------------------------------------------------------
// Launch. Input order (metadata): x, rank_masks, vals, he_idxs, rows, cols.
// (JAX without x64 downcasts the "int64" index arrays to int32.)
// ---------------------------------------------------------------------------
extern "C" void kernel_launch(void* const* d_in, const int* in_sizes, int n_in,
                              void* d_out, int out_size) {
    const float* x   = (const float*)d_in[0];
    const float* rm  = (const float*)d_in[1];
    const float* val = (const float*)d_in[2];
    const int*   he  = (const int*)d_in[3];
    const int*   rw  = (const int*)d_in[4];
    const int*   cl  = (const int*)d_in[5];
    float* out = (float*)d_out;

    const int TPB = 256;

    k_zero <<<(MBK + TPB - 1) / TPB, TPB>>>();
    k_count<<<(NNZV + TPB - 1) / TPB, TPB>>>(rw, cl);
    k_scan1<<<NBLK, 256>>>();
    k_scan2<<<1, 256>>>();
    k_scan3<<<(MBK + TPB - 1) / TPB, TPB>>>();
    k_fill <<<(NNZV + TPB - 1) / TPB, TPB>>>(rw, cl, val);

    const unsigned GW = (unsigned)EE * 16;   // 1.6M threads per gather pass
    k_fwd<<<(GW + TPB - 1) / TPB, TPB>>>((const float4*)x);
    k_bwd<<<(GW + TPB - 1) / TPB, TPB>>>((float4*)out, (const float4*)x, rm, he);
}